// round 1
// baseline (speedup 1.0000x reference)
#include <cuda_runtime.h>
#include <cuda_bf16.h>

#define BATCH 4096
#define TT    512
#define IN    20
#define HID   51
#define NG    204   // 4*HID

__device__ __forceinline__ float sigmoidf_(float v) { return 1.0f / (1.0f + expf(-v)); }

__global__ __launch_bounds__(256, 2) void lstm_fused_kernel(
    const float* __restrict__ x,
    const float* __restrict__ W_ih1, const float* __restrict__ W_hh1,
    const float* __restrict__ b_ih1, const float* __restrict__ b_hh1,
    const float* __restrict__ W_ih2, const float* __restrict__ W_hh2,
    const float* __restrict__ b_ih2, const float* __restrict__ b_hh2,
    const float* __restrict__ W_mu,  const float* __restrict__ b_mu,
    const float* __restrict__ W_lv,  const float* __restrict__ b_lv,
    float* __restrict__ out)
{
    const int b   = blockIdx.x;
    const int tid = threadIdx.x;

    __shared__ __align__(16) float h_sh[52];   // layer-1 hidden state (51 + pad)
    __shared__ __align__(16) float xs[20];     // current timestep input
    __shared__ float gates_sh[NG];

    // ---- per-thread layer-1 weights in registers (71 floats) ----
    float wx[IN]; float wh[HID]; float bias = 0.f;
    if (tid < NG) {
        #pragma unroll
        for (int k = 0; k < IN; k++)  wx[k] = W_ih1[tid * IN + k];
        #pragma unroll
        for (int k = 0; k < HID; k++) wh[k] = W_hh1[tid * HID + k];
        bias = b_ih1[tid] + b_hh1[tid];
    }
    float c1 = 0.f;  // thread u (<51) also owns cell state c1[u]

    // ---- warp 7 (tid 224..255) owns layer 2 ----
    const int lane = tid - 224;
    float w2a[4], w2b[4], bias2[4], whh2[4];
    float c2 = 0.f, h2 = 0.f, sum_h2 = 0.f;
    if (tid >= 224) {
        #pragma unroll
        for (int g = 0; g < 4; g++) {
            w2a[g]   = W_ih2[g * HID + lane];                              // lane 0..31 < 51
            w2b[g]   = (lane < HID - 32) ? W_ih2[g * HID + lane + 32] : 0.f;
            bias2[g] = b_ih2[g] + b_hh2[g];
            whh2[g]  = W_hh2[g];
        }
    }

    if (tid < 52) h_sh[tid] = 0.f;
    if (tid >= 204 && tid < 204 + IN)
        xs[tid - 204] = x[(b * TT + 0) * IN + (tid - 204)];
    __syncthreads();

    const float4* xs4 = reinterpret_cast<const float4*>(xs);
    const float4* h4  = reinterpret_cast<const float4*>(h_sh);

    for (int t = 0; t < TT; t++) {
        // ---- phase 0: all 204 gate rows in parallel ----
        if (tid < NG) {
            float acc = bias;
            #pragma unroll
            for (int k4 = 0; k4 < 5; k4++) {
                float4 v = xs4[k4];
                acc += wx[k4*4+0]*v.x; acc += wx[k4*4+1]*v.y;
                acc += wx[k4*4+2]*v.z; acc += wx[k4*4+3]*v.w;
            }
            #pragma unroll
            for (int k4 = 0; k4 < 12; k4++) {
                float4 v = h4[k4];
                acc += wh[k4*4+0]*v.x; acc += wh[k4*4+1]*v.y;
                acc += wh[k4*4+2]*v.z; acc += wh[k4*4+3]*v.w;
            }
            acc += wh[48]*h_sh[48]; acc += wh[49]*h_sh[49]; acc += wh[50]*h_sh[50];
            gates_sh[tid] = acc;
        }
        __syncthreads();   // gates visible; h_sh/xs free to overwrite

        // ---- phase 1: layer-1 state update (threads 0..50) ----
        if (tid < HID) {
            float ig = sigmoidf_(gates_sh[tid]);
            float fg = sigmoidf_(gates_sh[HID   + tid]);
            float gg = tanhf    (gates_sh[2*HID + tid]);
            float og = sigmoidf_(gates_sh[3*HID + tid]);
            c1 = fg * c1 + ig * gg;
            h_sh[tid] = og * tanhf(c1);
        }
        // prefetch next-step x (threads 204..223)
        if (t + 1 < TT && tid >= 204 && tid < 204 + IN)
            xs[tid - 204] = x[(b * TT + t + 1) * IN + (tid - 204)];
        __syncthreads();   // new h1 visible

        // ---- phase 2: layer 2 on warp 7 (overlaps next-iter gate compute timing-wise) ----
        if (tid >= 224) {
            float h1a = h_sh[lane];
            float h1b = (lane < HID - 32) ? h_sh[lane + 32] : 0.f;
            float pg[4];
            #pragma unroll
            for (int g = 0; g < 4; g++) {
                float p = w2a[g] * h1a + w2b[g] * h1b;
                p += __shfl_down_sync(0xffffffffu, p, 16);
                p += __shfl_down_sync(0xffffffffu, p, 8);
                p += __shfl_down_sync(0xffffffffu, p, 4);
                p += __shfl_down_sync(0xffffffffu, p, 2);
                p += __shfl_down_sync(0xffffffffu, p, 1);
                pg[g] = p;
            }
            if (lane == 0) {
                float i2 = sigmoidf_(pg[0] + bias2[0] + whh2[0] * h2);
                float f2 = sigmoidf_(pg[1] + bias2[1] + whh2[1] * h2);
                float g2 = tanhf    (pg[2] + bias2[2] + whh2[2] * h2);
                float o2 = sigmoidf_(pg[3] + bias2[3] + whh2[3] * h2);
                c2 = f2 * c2 + i2 * g2;
                h2 = o2 * tanhf(c2);
                sum_h2 += h2;
            }
        }
    }

    // ---- epilogue: mean over T, mu / log_var heads, interval ----
    if (tid == 224) {
        float agg = sum_h2 * (1.0f / TT);
        float mu  = W_mu[0] * agg + b_mu[0];
        float lv  = W_lv[0] * agg + b_lv[0];
        float sg  = expf(0.5f * lv);
        out[b]             = mu - 1.96f * sg;   // lower
        out[BATCH + b]     = mu;                // mu
        out[2 * BATCH + b] = mu + 1.96f * sg;   // upper
        out[3 * BATCH + b] = lv;                // log_var
    }
}

extern "C" void kernel_launch(void* const* d_in, const int* in_sizes, int n_in,
                              void* d_out, int out_size) {
    const float* x     = (const float*)d_in[0];
    const float* W_ih1 = (const float*)d_in[1];
    const float* W_hh1 = (const float*)d_in[2];
    const float* b_ih1 = (const float*)d_in[3];
    const float* b_hh1 = (const float*)d_in[4];
    const float* W_ih2 = (const float*)d_in[5];
    const float* W_hh2 = (const float*)d_in[6];
    const float* b_ih2 = (const float*)d_in[7];
    const float* b_hh2 = (const float*)d_in[8];
    const float* W_mu  = (const float*)d_in[9];
    const float* b_mu  = (const float*)d_in[10];
    const float* W_lv  = (const float*)d_in[11];
    const float* b_lv  = (const float*)d_in[12];
    float* out = (float*)d_out;

    lstm_fused_kernel<<<BATCH, 256>>>(x, W_ih1, W_hh1, b_ih1, b_hh1,
                                      W_ih2, W_hh2, b_ih2, b_hh2,
                                      W_mu, b_mu, W_lv, b_lv, out);
}

// round 2
// speedup vs baseline: 1.8220x; 1.8220x over previous
#include <cuda_runtime.h>
#include <cuda_bf16.h>

#define BATCH 4096
#define TT    512
#define IN    20
#define HID   51
#define NG    204   // 4*HID
#define SPB   8     // sequences per block
#define NBLK  (BATCH / SPB)   // 512 blocks

// ---- packed f32x2 helpers (sm_103a) ----
__device__ __forceinline__ unsigned long long pack2(float v) {
    unsigned long long r;
    asm("mov.b64 %0, {%1, %1};" : "=l"(r) : "f"(v));
    return r;
}
__device__ __forceinline__ unsigned long long fma2(unsigned long long a,
                                                   unsigned long long b,
                                                   unsigned long long c) {
    unsigned long long d;
    asm("fma.rn.f32x2 %0, %1, %2, %3;" : "=l"(d) : "l"(a), "l"(b), "l"(c));
    return d;
}

// ---- fast activations: MUFU ex2 + rcp, rel err ~1e-6 (plenty vs 1e-3 tol) ----
__device__ __forceinline__ float fsig(float x)  { return __fdividef(1.0f, 1.0f + __expf(-x)); }
__device__ __forceinline__ float ftanh_(float x){ return 1.0f - __fdividef(2.0f, __expf(2.0f * x) + 1.0f); }

__global__ __launch_bounds__(256, 1) void lstm8_kernel(
    const float* __restrict__ x,
    const float* __restrict__ W_ih1, const float* __restrict__ W_hh1,
    const float* __restrict__ b_ih1, const float* __restrict__ b_hh1,
    const float* __restrict__ W_ih2, const float* __restrict__ W_hh2,
    const float* __restrict__ b_ih2, const float* __restrict__ b_hh2,
    const float* __restrict__ W_mu,  const float* __restrict__ b_mu,
    const float* __restrict__ W_lv,  const float* __restrict__ b_lv,
    float* __restrict__ out)
{
    const int b8  = blockIdx.x * SPB;
    const int tid = threadIdx.x;

    // seq-packed layouts: [k][seq] so one LDS.128 = seqs 0..3 (= two f32x2 pairs)
    __shared__ __align__(16) float x_sh[2][IN][SPB];      // double-buffered input
    __shared__ __align__(16) float h_sh[HID][SPB];        // layer-1 hidden state
    __shared__ __align__(16) float gates_sh[NG][SPB];     // raw gate pre-activations
    __shared__ float w2_sh[NG];                           // W_ih2 transposed [u*4+g]

    // ---- per-thread layer-1 weights, packed {w,w} (142 regs) ----
    unsigned long long wxp[IN], whp[HID], biasp = 0ULL;
    if (tid < NG) {
        #pragma unroll
        for (int k = 0; k < IN;  k++) wxp[k] = pack2(W_ih1[tid * IN  + k]);
        #pragma unroll
        for (int k = 0; k < HID; k++) whp[k] = pack2(W_hh1[tid * HID + k]);
        biasp = pack2(b_ih1[tid] + b_hh1[tid]);
        w2_sh[tid] = W_ih2[(tid & 3) * HID + (tid >> 2)];
        int u = tid >> 2, s = tid & 3;
        h_sh[u][s] = 0.f; h_sh[u][s + 4] = 0.f;
    }
    float c1a = 0.f, c1b = 0.f;   // cell state for (s,u) and (s+4,u)

    // ---- warp 7: layer 2, lane = (s2, g2), pipelined one step behind ----
    const int lane = tid - 224;
    const int s2 = lane >> 2, g2 = lane & 3;
    float l2_bias = 0.f, l2_whh = 0.f;
    float c2 = 0.f, h2 = 0.f, sum_h2 = 0.f;
    if (tid >= 224) {
        l2_bias = b_ih2[g2] + b_hh2[g2];
        l2_whh  = W_hh2[g2];
    }

    // ---- preload x[t=0] into buffer 0 (threads 204..223) ----
    if (tid >= NG && tid < NG + IN) {
        int j = tid - NG;
        {
            int s = j / 5, c = j % 5;
            float4 v = *reinterpret_cast<const float4*>(
                &x[((size_t)(b8 + s) * TT + 0) * IN + 4 * c]);
            x_sh[0][4*c+0][s] = v.x; x_sh[0][4*c+1][s] = v.y;
            x_sh[0][4*c+2][s] = v.z; x_sh[0][4*c+3][s] = v.w;
        }
        {
            int j2 = j + IN; int s = j2 / 5, c = j2 % 5;
            float4 v = *reinterpret_cast<const float4*>(
                &x[((size_t)(b8 + s) * TT + 0) * IN + 4 * c]);
            x_sh[0][4*c+0][s] = v.x; x_sh[0][4*c+1][s] = v.y;
            x_sh[0][4*c+2][s] = v.z; x_sh[0][4*c+3][s] = v.w;
        }
    }
    __syncthreads();

    float4 xr0 = make_float4(0,0,0,0), xr1 = make_float4(0,0,0,0);

    #pragma unroll 1
    for (int t = 0; t < TT; t++) {
        // ============ phase 0 ============
        if (tid < NG) {
            // gate row `tid` for 8 sequences: 4 independent FFMA2 chains
            unsigned long long a0 = biasp, a1 = biasp, a2 = biasp, a3 = biasp;
            const int buf = t & 1;
            #pragma unroll
            for (int k = 0; k < IN; k++) {
                ulonglong2 p = *reinterpret_cast<const ulonglong2*>(&x_sh[buf][k][0]);
                ulonglong2 q = *reinterpret_cast<const ulonglong2*>(&x_sh[buf][k][4]);
                a0 = fma2(wxp[k], p.x, a0); a1 = fma2(wxp[k], p.y, a1);
                a2 = fma2(wxp[k], q.x, a2); a3 = fma2(wxp[k], q.y, a3);
            }
            #pragma unroll
            for (int k = 0; k < HID; k++) {
                ulonglong2 p = *reinterpret_cast<const ulonglong2*>(&h_sh[k][0]);
                ulonglong2 q = *reinterpret_cast<const ulonglong2*>(&h_sh[k][4]);
                a0 = fma2(whp[k], p.x, a0); a1 = fma2(whp[k], p.y, a1);
                a2 = fma2(whp[k], q.x, a2); a3 = fma2(whp[k], q.y, a3);
            }
            *reinterpret_cast<ulonglong2*>(&gates_sh[tid][0]) = make_ulonglong2(a0, a1);
            *reinterpret_cast<ulonglong2*>(&gates_sh[tid][4]) = make_ulonglong2(a2, a3);
        } else if (tid < NG + IN) {
            // x prefetch for t+1 into registers (latency hidden by phase 0)
            if (t + 1 < TT) {
                int j = tid - NG;
                int sa = j / 5,       ca = j % 5;
                int j2 = j + IN, sb = j2 / 5, cb = j2 % 5;
                xr0 = *reinterpret_cast<const float4*>(
                    &x[((size_t)(b8 + sa) * TT + t + 1) * IN + 4 * ca]);
                xr1 = *reinterpret_cast<const float4*>(
                    &x[((size_t)(b8 + sb) * TT + t + 1) * IN + 4 * cb]);
            }
        } else {
            // warp 7: layer 2 for step t-1, reading h_sh = h1[t-1]
            float acc0 = 0.f, acc1 = 0.f, acc2 = 0.f;
            #pragma unroll
            for (int u = 0; u < HID; u += 3) {
                acc0 += w2_sh[(u+0)*4 + g2] * h_sh[u+0][s2];
                acc1 += w2_sh[(u+1)*4 + g2] * h_sh[u+1][s2];
                acc2 += w2_sh[(u+2)*4 + g2] * h_sh[u+2][s2];
            }
            float p = acc0 + acc1 + acc2;
            float pf = __shfl_sync(0xffffffffu, p, (s2 << 2) | 1);
            float pg = __shfl_sync(0xffffffffu, p, (s2 << 2) | 2);
            float po = __shfl_sync(0xffffffffu, p, (s2 << 2) | 3);
            float bf = __shfl_sync(0xffffffffu, l2_bias, (s2 << 2) | 1);
            float bg = __shfl_sync(0xffffffffu, l2_bias, (s2 << 2) | 2);
            float bo = __shfl_sync(0xffffffffu, l2_bias, (s2 << 2) | 3);
            float wf = __shfl_sync(0xffffffffu, l2_whh, (s2 << 2) | 1);
            float wg = __shfl_sync(0xffffffffu, l2_whh, (s2 << 2) | 2);
            float wo = __shfl_sync(0xffffffffu, l2_whh, (s2 << 2) | 3);
            if (t > 0 && g2 == 0) {
                float i2 = fsig  (p  + l2_bias + l2_whh * h2);
                float f2 = fsig  (pf + bf + wf * h2);
                float g2v= ftanh_(pg + bg + wg * h2);
                float o2 = fsig  (po + bo + wo * h2);
                c2 = f2 * c2 + i2 * g2v;
                h2 = o2 * ftanh_(c2);
                sum_h2 += h2;
            }
        }
        __syncthreads();

        // ============ phase 1 ============
        if (tid < NG) {
            const int u = tid >> 2, s = tid & 3;
            {
                float gi = gates_sh[u][s];
                float gf = gates_sh[HID   + u][s];
                float gg = gates_sh[2*HID + u][s];
                float go = gates_sh[3*HID + u][s];
                c1a = fsig(gf) * c1a + fsig(gi) * ftanh_(gg);
                h_sh[u][s] = fsig(go) * ftanh_(c1a);
            }
            {
                const int sb = s + 4;
                float gi = gates_sh[u][sb];
                float gf = gates_sh[HID   + u][sb];
                float gg = gates_sh[2*HID + u][sb];
                float go = gates_sh[3*HID + u][sb];
                c1b = fsig(gf) * c1b + fsig(gi) * ftanh_(gg);
                h_sh[u][sb] = fsig(go) * ftanh_(c1b);
            }
        } else if (tid < NG + IN) {
            if (t + 1 < TT) {
                int j = tid - NG;
                int sa = j / 5,       ca = j % 5;
                int j2 = j + IN, sb = j2 / 5, cb = j2 % 5;
                const int nb = (t + 1) & 1;
                x_sh[nb][4*ca+0][sa] = xr0.x; x_sh[nb][4*ca+1][sa] = xr0.y;
                x_sh[nb][4*ca+2][sa] = xr0.z; x_sh[nb][4*ca+3][sa] = xr0.w;
                x_sh[nb][4*cb+0][sb] = xr1.x; x_sh[nb][4*cb+1][sb] = xr1.y;
                x_sh[nb][4*cb+2][sb] = xr1.z; x_sh[nb][4*cb+3][sb] = xr1.w;
            }
        }
        __syncthreads();
    }

    // ---- final layer-2 step (t = TT-1) + epilogue ----
    if (tid >= 224) {
        float acc0 = 0.f, acc1 = 0.f, acc2 = 0.f;
        #pragma unroll
        for (int u = 0; u < HID; u += 3) {
            acc0 += w2_sh[(u+0)*4 + g2] * h_sh[u+0][s2];
            acc1 += w2_sh[(u+1)*4 + g2] * h_sh[u+1][s2];
            acc2 += w2_sh[(u+2)*4 + g2] * h_sh[u+2][s2];
        }
        float p = acc0 + acc1 + acc2;
        float pf = __shfl_sync(0xffffffffu, p, (s2 << 2) | 1);
        float pg = __shfl_sync(0xffffffffu, p, (s2 << 2) | 2);
        float po = __shfl_sync(0xffffffffu, p, (s2 << 2) | 3);
        float bf = __shfl_sync(0xffffffffu, l2_bias, (s2 << 2) | 1);
        float bg = __shfl_sync(0xffffffffu, l2_bias, (s2 << 2) | 2);
        float bo = __shfl_sync(0xffffffffu, l2_bias, (s2 << 2) | 3);
        float wf = __shfl_sync(0xffffffffu, l2_whh, (s2 << 2) | 1);
        float wg = __shfl_sync(0xffffffffu, l2_whh, (s2 << 2) | 2);
        float wo = __shfl_sync(0xffffffffu, l2_whh, (s2 << 2) | 3);
        if (g2 == 0) {
            float i2 = fsig  (p  + l2_bias + l2_whh * h2);
            float f2 = fsig  (pf + bf + wf * h2);
            float g2v= ftanh_(pg + bg + wg * h2);
            float o2 = fsig  (po + bo + wo * h2);
            c2 = f2 * c2 + i2 * g2v;
            h2 = o2 * ftanh_(c2);
            sum_h2 += h2;

            // mean over T, heads, interval
            float agg = sum_h2 * (1.0f / TT);
            float mu  = W_mu[0] * agg + b_mu[0];
            float lv  = W_lv[0] * agg + b_lv[0];
            float sg  = __expf(0.5f * lv);
            int b = b8 + s2;
            out[b]             = mu - 1.96f * sg;
            out[BATCH + b]     = mu;
            out[2*BATCH + b]   = mu + 1.96f * sg;
            out[3*BATCH + b]   = lv;
        }
    }
}

extern "C" void kernel_launch(void* const* d_in, const int* in_sizes, int n_in,
                              void* d_out, int out_size) {
    const float* x     = (const float*)d_in[0];
    const float* W_ih1 = (const float*)d_in[1];
    const float* W_hh1 = (const float*)d_in[2];
    const float* b_ih1 = (const float*)d_in[3];
    const float* b_hh1 = (const float*)d_in[4];
    const float* W_ih2 = (const float*)d_in[5];
    const float* W_hh2 = (const float*)d_in[6];
    const float* b_ih2 = (const float*)d_in[7];
    const float* b_hh2 = (const float*)d_in[8];
    const float* W_mu  = (const float*)d_in[9];
    const float* b_mu  = (const float*)d_in[10];
    const float* W_lv  = (const float*)d_in[11];
    const float* b_lv  = (const float*)d_in[12];
    float* out = (float*)d_out;

    lstm8_kernel<<<NBLK, 256>>>(x, W_ih1, W_hh1, b_ih1, b_hh1,
                                W_ih2, W_hh2, b_ih2, b_hh2,
                                W_mu, b_mu, W_lv, b_lv, out);
}